// round 5
// baseline (speedup 1.0000x reference)
#include <cuda_runtime.h>
#include <cuda_bf16.h>
#include <math.h>

#define A_   128
#define D_   128
#define DM1  127
#define MAXB 64

// T probabilities, bf16. Layout (uint4 units):
//   idx4 = (d*64 + w*8 + q)*32 + lane
// holding {T[kb+2q][4l..4l+3], T[kb+2q+1][4l..4l+3]} where kb = 16*w.
// Consecutive lanes -> consecutive uint4: every warp LDG.128 is one 512B run.
__device__ uint2  g_T[(size_t)DM1 * A_ * A_ / 4];   // viewed as uint4[...]
// Emission table: {sigmoid(l), sigmoid(-l)} = {p(x=1|a), p(x=0|a)} per (d,j).
__device__ float2 g_S2[D_ * A_];
// Initial-state probabilities (softmax of u_log_p_a1).
__device__ float  g_pa1[A_];

// ---------------------------------------------------------------------------
// Prep A: row softmax of u_log_transition -> g_T (bf16, packed layout above).
// ---------------------------------------------------------------------------
__global__ void k_prepT(const float* __restrict__ u) {
    int w = threadIdx.x >> 5, lane = threadIdx.x & 31;
    int row = blockIdx.x * 8 + w;
    if (row >= DM1 * A_) return;
    float4 v4 = reinterpret_cast<const float4*>(u)[(size_t)row * 32 + lane];
    float m = fmaxf(fmaxf(v4.x, v4.y), fmaxf(v4.z, v4.w));
    #pragma unroll
    for (int o = 16; o > 0; o >>= 1) m = fmaxf(m, __shfl_xor_sync(0xffffffffu, m, o));
    float e0 = __expf(v4.x - m), e1 = __expf(v4.y - m);
    float e2 = __expf(v4.z - m), e3 = __expf(v4.w - m);
    float s = e0 + e1 + e2 + e3;
    #pragma unroll
    for (int o = 16; o > 0; o >>= 1) s += __shfl_xor_sync(0xffffffffu, s, o);
    float inv = 1.0f / s;
    __nv_bfloat162 p0 = __floats2bfloat162_rn(e0 * inv, e1 * inv);  // lo=j0, hi=j1
    __nv_bfloat162 p1 = __floats2bfloat162_rn(e2 * inv, e3 * inv);  // lo=j2, hi=j3
    uint2 ov;
    ov.x = *reinterpret_cast<unsigned int*>(&p0);
    ov.y = *reinterpret_cast<unsigned int*>(&p1);
    int d  = row >> 7;
    int k  = row & (A_ - 1);
    int wt = k >> 4;
    int kk = k & 15;
    size_t i2 = (((size_t)d * 64 + wt * 8 + (kk >> 1)) * 32 + lane) * 2 + (kk & 1);
    g_T[i2] = ov;
}

// ---------------------------------------------------------------------------
// Prep B: emission sigmoid table.
// ---------------------------------------------------------------------------
__global__ void k_prepS(const float* __restrict__ lpx) {
    int i = blockIdx.x * 256 + threadIdx.x;
    if (i < D_ * A_) {
        float l = lpx[i];
        g_S2[i] = make_float2(1.0f / (1.0f + __expf(-l)),
                              1.0f / (1.0f + __expf(l)));
    }
}

// ---------------------------------------------------------------------------
// Prep C: softmax of u_log_p_a1 -> g_pa1; writes log_p_a1 output tail.
// ---------------------------------------------------------------------------
__global__ void k_pa1(const float* __restrict__ u, float* __restrict__ out,
                      int base, int out_size) {
    __shared__ float sred[4];
    int t = threadIdx.x, lane = t & 31, w = t >> 5;
    float v = u[t];
    float m = v;
    #pragma unroll
    for (int o = 16; o > 0; o >>= 1) m = fmaxf(m, __shfl_xor_sync(0xffffffffu, m, o));
    if (lane == 0) sred[w] = m;
    __syncthreads();
    m = fmaxf(fmaxf(sred[0], sred[1]), fmaxf(sred[2], sred[3]));
    __syncthreads();
    float e = __expf(v - m);
    float s = e;
    #pragma unroll
    for (int o = 16; o > 0; o >>= 1) s += __shfl_xor_sync(0xffffffffu, s, o);
    if (lane == 0) sred[w] = s;
    __syncthreads();
    s = sred[0] + sred[1] + sred[2] + sred[3];
    float lp = v - m - logf(s);
    g_pa1[t] = __expf(lp);
    int idx = base + t;
    if (idx < out_size) out[idx] = lp;
}

// ---------------------------------------------------------------------------
// Main forward recurrence, 2 batch elements per CTA. grid = B/2, block = 256.
// Warp w owns k/j slice [16w,16w+16). Lanes 0-15 carry b0's v for that slice,
// lanes 16-31 carry b1's. Same T registers serve both b's. One barrier/step.
// Partials: b0 region and b1 region bank-shifted by 16 floats (conflict-free).
// ---------------------------------------------------------------------------
#define P_B1_OFF (2 * 8 * A_ + 16)   // float offset of b1 partial region

__global__ void __launch_bounds__(256, 1) k_forward(const float* __restrict__ x,
                                                    float* __restrict__ out,
                                                    int out_size, int B) {
    const int b0 = 2 * blockIdx.x;
    const int b1 = (b0 + 1 < B) ? b0 + 1 : b0;
    const int t = threadIdx.x;
    const int w = t >> 5, lane = t & 31;
    const int kb = w * 16;
    const int half = lane >> 4;            // 0 -> b0, 1 -> b1
    const int jj = kb + (lane & 15);       // this thread's owned j (combine/v)

    // part[b][buf][w][128] with +16-float shift for b=1
    __shared__ float part[2 * (2 * 8 * A_) + 16];
    __shared__ float s_red[8][2];
    __shared__ float sx2[2][D_];

    if (t < D_) sx2[0][t] = x[b0 * D_ + t];
    else        sx2[1][t - 128] = x[b1 * D_ + (t - 128)];
    __syncthreads();

    const int myb = half;                  // emission/x row for this thread
    float v_reg, acc = 0.f, e_pref;
    {
        float2 s0 = g_S2[jj];
        v_reg = ((sx2[myb][0] > 0.5f) ? s0.x : s0.y) * g_pa1[jj];
        float2 s1 = g_S2[A_ + jj];
        e_pref = (sx2[myb][1] > 0.5f) ? s1.x : s1.y;
    }

    // per-warp T base in uint4 units; +d*2048 per matrix; +q*32 per pair-row
    const uint4* Tbase = reinterpret_cast<const uint4*>(g_T) +
                         (size_t)w * 8 * 32 + lane;

    uint4 TA[8], TB[8];
    #pragma unroll
    for (int q = 0; q < 8; ++q) TA[q] = Tbase[q * 32];   // d-matrix 0
    int buf = 0;

#define PREFETCH_T(DST, DMAT) do {                                          \
        const uint4* _tp = Tbase + (size_t)(DMAT) * 2048;                   \
        _Pragma("unroll")                                                   \
        for (int q = 0; q < 8; ++q) (DST)[q] = _tp[q * 32];                 \
    } while (0)

#define STEP(DD, TARR) do {                                                 \
        float a00 = 0.f, a01 = 0.f, a02 = 0.f, a03 = 0.f;                   \
        float a10 = 0.f, a11 = 0.f, a12 = 0.f, a13 = 0.f;                   \
        _Pragma("unroll")                                                   \
        for (int q = 0; q < 8; ++q) {                                       \
            float u00 = __shfl_sync(0xffffffffu, v_reg, 2 * q);             \
            float u01 = __shfl_sync(0xffffffffu, v_reg, 2 * q + 1);         \
            float u10 = __shfl_sync(0xffffffffu, v_reg, 16 + 2 * q);        \
            float u11 = __shfl_sync(0xffffffffu, v_reg, 17 + 2 * q);        \
            uint4 r = (TARR)[q];                                            \
            float f0 = __uint_as_float(r.x << 16);                          \
            float f1 = __uint_as_float(r.x & 0xffff0000u);                  \
            float f2 = __uint_as_float(r.y << 16);                          \
            float f3 = __uint_as_float(r.y & 0xffff0000u);                  \
            float g0 = __uint_as_float(r.z << 16);                          \
            float g1 = __uint_as_float(r.z & 0xffff0000u);                  \
            float g2 = __uint_as_float(r.w << 16);                          \
            float g3 = __uint_as_float(r.w & 0xffff0000u);                  \
            a00 = fmaf(u00, f0, a00); a01 = fmaf(u00, f1, a01);             \
            a02 = fmaf(u00, f2, a02); a03 = fmaf(u00, f3, a03);             \
            a00 = fmaf(u01, g0, a00); a01 = fmaf(u01, g1, a01);             \
            a02 = fmaf(u01, g2, a02); a03 = fmaf(u01, g3, a03);             \
            a10 = fmaf(u10, f0, a10); a11 = fmaf(u10, f1, a11);             \
            a12 = fmaf(u10, f2, a12); a13 = fmaf(u10, f3, a13);             \
            a10 = fmaf(u11, g0, a10); a11 = fmaf(u11, g1, a11);             \
            a12 = fmaf(u11, g2, a12); a13 = fmaf(u11, g3, a13);             \
        }                                                                   \
        *reinterpret_cast<float4*>(&part[buf * (8 * A_) + w * A_ + 4 * lane]) \
            = make_float4(a00, a01, a02, a03);                              \
        *reinterpret_cast<float4*>(&part[P_B1_OFF + buf * (8 * A_) + w * A_ + 4 * lane]) \
            = make_float4(a10, a11, a12, a13);                              \
        __syncthreads();                                                    \
        {                                                                   \
            const float* pb = &part[half * P_B1_OFF + buf * (8 * A_) + jj]; \
            float p0 = pb[0 * A_], p1 = pb[1 * A_];                         \
            float p2 = pb[2 * A_], p3 = pb[3 * A_];                         \
            float p4 = pb[4 * A_], p5 = pb[5 * A_];                         \
            float p6 = pb[6 * A_], p7 = pb[7 * A_];                         \
            float s = ((p0 + p1) + (p2 + p3)) + ((p4 + p5) + (p6 + p7));    \
            v_reg = s * e_pref;                                             \
            int dn = ((DD) + 1 < D_) ? (DD) + 1 : (DD);                     \
            float2 sn = g_S2[dn * A_ + jj];                                 \
            e_pref = (sx2[myb][dn] > 0.5f) ? sn.x : sn.y;                   \
        }                                                                   \
        if (((DD) & 15) == 15) {                                            \
            float m = v_reg;                                                \
            m = fmaxf(m, __shfl_xor_sync(0xffffffffu, m, 8, 16));           \
            m = fmaxf(m, __shfl_xor_sync(0xffffffffu, m, 4, 16));           \
            m = fmaxf(m, __shfl_xor_sync(0xffffffffu, m, 2, 16));           \
            m = fmaxf(m, __shfl_xor_sync(0xffffffffu, m, 1, 16));           \
            if ((lane & 15) == 0) s_red[w][half] = m;                       \
            __syncthreads();                                                \
            float mm = fmaxf(                                               \
                fmaxf(fmaxf(s_red[0][half], s_red[1][half]),                \
                      fmaxf(s_red[2][half], s_red[3][half])),               \
                fmaxf(fmaxf(s_red[4][half], s_red[5][half]),                \
                      fmaxf(s_red[6][half], s_red[7][half])));              \
            v_reg *= (1.0f / mm);                                           \
            acc += __logf(mm);                                              \
        }                                                                   \
        buf ^= 1;                                                           \
    } while (0)

    // steps d = 1 .. 126 in pairs, double-buffered T
    for (int i = 1; i < DM1; i += 2) {
        PREFETCH_T(TB, i);                           // T[i] used at step i+1
        STEP(i, TA);
        PREFETCH_T(TA, (i + 1 < DM1) ? (i + 1) : i); // T[i+1] used at step i+2
        STEP(i + 1, TB);
    }
    STEP(DM1, TA);                                   // d=127 uses T[126]

#undef STEP
#undef PREFETCH_T

    // final: log_px[b] = acc + log(sum_j v[j]) (per 16-lane group / per b)
    float sv = v_reg;
    sv += __shfl_xor_sync(0xffffffffu, sv, 8, 16);
    sv += __shfl_xor_sync(0xffffffffu, sv, 4, 16);
    sv += __shfl_xor_sync(0xffffffffu, sv, 2, 16);
    sv += __shfl_xor_sync(0xffffffffu, sv, 1, 16);
    if ((lane & 15) == 0) s_red[w][half] = sv;
    __syncthreads();
    float tot = ((s_red[0][half] + s_red[1][half]) + (s_red[2][half] + s_red[3][half]))
              + ((s_red[4][half] + s_red[5][half]) + (s_red[6][half] + s_red[7][half]));
    float res = acc + __logf(tot);
    int bb = half ? b1 : b0;
    int idx = bb * A_ + jj;
    if (idx < out_size) out[idx] = res;
}

// ---------------------------------------------------------------------------
extern "C" void kernel_launch(void* const* d_in, const int* in_sizes, int n_in,
                              void* d_out, int out_size) {
    const float* x     = (const float*)d_in[0];   // [B, D]
    const float* u_pa1 = (const float*)d_in[1];   // [1,1,1,A]
    const float* u_T   = (const float*)d_in[2];   // [D-1, A, A]
    const float* lpx   = (const float*)d_in[3];   // [1, D, 1, A]
    float* out = (float*)d_out;

    int B = in_sizes[0] / D_;
    if (B > MAXB) B = MAXB;

    k_prepT<<<(DM1 * A_ + 7) / 8, 256>>>(u_T);
    k_prepS<<<(D_ * A_ + 255) / 256, 256>>>(lpx);
    k_pa1<<<1, 128>>>(u_pa1, out, B * A_, out_size);

    k_forward<<<(B + 1) / 2, 256>>>(x, out, out_size, B);
}